// round 2
// baseline (speedup 1.0000x reference)
#include <cuda_runtime.h>
#include <math.h>

#define NN 50000
#define EE 1600000
#define GG 500
#define HH 128
#define NGG 50
#define LL 6

// ---------------- device scratch (static, no allocation) ----------------
__device__ int   g_cnt[NN];
__device__ int   g_rowptr[NN + 1];
__device__ int   g_cursor[NN];
__device__ int   g_scol[EE];
__device__ float g_sdist[EE];
__device__ float g_v[(size_t)NN * HH];        // node features [N,128]
__device__ float g_P[(size_t)NN * 256];       // [P0 | P1] per node
__device__ float g_M[(size_t)LL * 256 * HH];  // folded layer matrices [M0;M1]
__device__ float g_t[(size_t)NN * 64];        // readout hidden

__device__ __forceinline__ float ssp_f(float x) {
  // softplus(x) - ln(2)
  float sp = (x > 15.f) ? x : __logf(1.f + __expf(x));
  return sp - 0.6931471805599453f;
}

// ---------------- CSR build ----------------
__global__ void k_zero_cnt() {
  int i = blockIdx.x * blockDim.x + threadIdx.x;
  if (i < NN) g_cnt[i] = 0;
}

__global__ void k_hist(const int* __restrict__ row) {
  int e = blockIdx.x * blockDim.x + threadIdx.x;
  if (e < EE) atomicAdd(&g_cnt[row[e]], 1);
}

// single-block inclusive scan -> exclusive rowptr
__global__ void k_scan() {
  __shared__ int wsum[32];
  __shared__ int s_carry;
  int tid = threadIdx.x, lane = tid & 31, wid = tid >> 5;
  if (tid == 0) { s_carry = 0; g_rowptr[0] = 0; }
  __syncthreads();
  for (int base = 0; base < NN; base += 1024) {
    int i = base + tid;
    int x = (i < NN) ? g_cnt[i] : 0;
    int incl = x;
#pragma unroll
    for (int off = 1; off < 32; off <<= 1) {
      int y = __shfl_up_sync(0xffffffffu, incl, off);
      if (lane >= off) incl += y;
    }
    if (lane == 31) wsum[wid] = incl;
    __syncthreads();
    if (wid == 0) {
      int wv = wsum[lane];
      int winc = wv;
#pragma unroll
      for (int off = 1; off < 32; off <<= 1) {
        int y = __shfl_up_sync(0xffffffffu, winc, off);
        if (lane >= off) winc += y;
      }
      wsum[lane] = winc - wv;  // exclusive warp offsets
    }
    __syncthreads();
    int carry = s_carry;
    int total_incl = incl + wsum[wid] + carry;
    if (i < NN) g_rowptr[i + 1] = total_incl;
    __syncthreads();
    if (tid == 1023) s_carry = total_incl;
    __syncthreads();
  }
}

__global__ void k_cursor() {
  int i = blockIdx.x * blockDim.x + threadIdx.x;
  if (i < NN) g_cursor[i] = g_rowptr[i];
}

__global__ void k_scatter(const int* __restrict__ row, const int* __restrict__ col,
                          const float* __restrict__ pos) {
  int e = blockIdx.x * blockDim.x + threadIdx.x;
  if (e >= EE) return;
  int r = row[e], c = col[e];
  float dx = pos[3 * r + 0] - pos[3 * c + 0];
  float dy = pos[3 * r + 1] - pos[3 * c + 1];
  float dz = pos[3 * r + 2] - pos[3 * c + 2];
  float dist = sqrtf(dx * dx + dy * dy + dz * dz);
  int idx = atomicAdd(&g_cursor[r], 1);
  g_scol[idx] = c;
  g_sdist[idx] = dist;
}

// ---------------- init & weight folding ----------------
__global__ void k_init_v(const int* __restrict__ z, const float* __restrict__ emb) {
  int i = blockIdx.x * blockDim.x + threadIdx.x;
  if (i < NN * HH) {
    int n = i >> 7, f = i & 127;
    g_v[i] = emb[(z[n] << 7) + f];
  }
}

// M0 = (Wn .* c) @ Wo ; M1 = (Wn .* a) @ Wo  with a = dist_W@We, c = dist_b@We + be
__global__ void k_prep(const float* __restrict__ dist_W, const float* __restrict__ dist_b,
                       const float* __restrict__ Wn, const float* __restrict__ We,
                       const float* __restrict__ be, const float* __restrict__ Wo) {
  int li = blockIdx.x;
  int tid = threadIdx.x;
  __shared__ float sa[128], sc[128];
  if (tid < 128) {
    float a = 0.f, c = 0.f;
    const float* we = We + (size_t)li * NGG * HH + tid;
#pragma unroll 10
    for (int g = 0; g < NGG; g++) {
      float w = we[(size_t)g * HH];
      a = fmaf(dist_W[g], w, a);
      c = fmaf(dist_b[g], w, c);
    }
    sa[tid] = a;
    sc[tid] = c + be[li * HH + tid];
  }
  __syncthreads();
  int k = blockIdx.y * 32 + (tid >> 3);  // 0..255
  int o0 = (tid & 7) << 4;               // 16 output cols
  int h = k & 127;
  const float* coef = (k >= 128) ? sa : sc;
  const float* wn = Wn + (size_t)li * HH * HH + (size_t)h * HH;
  const float* wo = Wo + (size_t)li * HH * HH + o0;
  float acc[16];
#pragma unroll
  for (int q = 0; q < 16; q++) acc[q] = 0.f;
  for (int f = 0; f < 128; f++) {
    float wf = wn[f] * coef[f];
    const float* wr = wo + (size_t)f * HH;
#pragma unroll
    for (int q = 0; q < 16; q++) acc[q] = fmaf(wf, wr[q], acc[q]);
  }
  float* dst = g_M + (size_t)li * 256 * HH + (size_t)k * HH + o0;
#pragma unroll
  for (int q = 0; q < 16; q++) dst[q] = acc[q];
}

// ---------------- edge aggregation: P0 = sum v[col], P1 = sum dist*v[col] ----------------
__global__ void k_edge() {
  int wg = (blockIdx.x * blockDim.x + threadIdx.x) >> 5;
  int lane = threadIdx.x & 31;
  if (wg >= NN) return;
  int s = g_rowptr[wg], e = g_rowptr[wg + 1];
  float4 a0 = make_float4(0.f, 0.f, 0.f, 0.f);
  float4 a1 = make_float4(0.f, 0.f, 0.f, 0.f);
  for (int base = s; base < e; base += 32) {
    int j = base + lane;
    int c = 0;
    float d = 0.f;
    if (j < e) { c = g_scol[j]; d = g_sdist[j]; }
    int cnt = min(32, e - base);
#pragma unroll 4
    for (int t = 0; t < cnt; ++t) {
      int cc = __shfl_sync(0xffffffffu, c, t);
      float dd = __shfl_sync(0xffffffffu, d, t);
      const float4 w = *(const float4*)(g_v + ((size_t)cc << 7) + (lane << 2));
      a0.x += w.x; a0.y += w.y; a0.z += w.z; a0.w += w.w;
      a1.x = fmaf(dd, w.x, a1.x);
      a1.y = fmaf(dd, w.y, a1.y);
      a1.z = fmaf(dd, w.z, a1.z);
      a1.w = fmaf(dd, w.w, a1.w);
    }
  }
  float* p = g_P + ((size_t)wg << 8);
  *(float4*)(p + (lane << 2)) = a0;
  *(float4*)(p + 128 + (lane << 2)) = a1;
}

// ---------------- layer GEMM: v = ssp(Pcat @ Mcat + bo) ; [N,256]x[256,128] ----------------
__global__ __launch_bounds__(256) void k_gemm(int layer, const float* __restrict__ bias) {
  __shared__ float As[8][128];
  __shared__ float Bs[8][128];
  const float* Bp = g_M + (size_t)layer * 256 * HH;
  int tid = threadIdx.x;
  int row0 = blockIdx.x * 128;
  int ty = tid >> 4, tx = tid & 15;
  float acc[8][8];
#pragma unroll
  for (int i = 0; i < 8; i++)
#pragma unroll
    for (int j = 0; j < 8; j++) acc[i][j] = 0.f;

  int a_r = tid >> 1, a_c = (tid & 1) << 2;
  int b_r = tid >> 5, b_c = (tid & 31) << 2;
  int grow = row0 + a_r;
  bool avalid = grow < NN;
  const float* Aptr = g_P + (size_t)(avalid ? grow : 0) * 256 + a_c;

  for (int k0 = 0; k0 < 256; k0 += 8) {
    float4 av = avalid ? *(const float4*)(Aptr + k0) : make_float4(0.f, 0.f, 0.f, 0.f);
    float4 bv = *(const float4*)(Bp + (size_t)(k0 + b_r) * 128 + b_c);
    As[a_c + 0][a_r] = av.x;
    As[a_c + 1][a_r] = av.y;
    As[a_c + 2][a_r] = av.z;
    As[a_c + 3][a_r] = av.w;
    *(float4*)&Bs[b_r][b_c] = bv;
    __syncthreads();
#pragma unroll
    for (int kk = 0; kk < 8; kk++) {
      float a[8], b[8];
      *(float4*)(a) = *(const float4*)&As[kk][ty * 8];
      *(float4*)(a + 4) = *(const float4*)&As[kk][ty * 8 + 4];
      *(float4*)(b) = *(const float4*)&Bs[kk][tx * 8];
      *(float4*)(b + 4) = *(const float4*)&Bs[kk][tx * 8 + 4];
#pragma unroll
      for (int i = 0; i < 8; i++)
#pragma unroll
        for (int j = 0; j < 8; j++) acc[i][j] = fmaf(a[i], b[j], acc[i][j]);
    }
    __syncthreads();
  }
#pragma unroll
  for (int i = 0; i < 8; i++) {
    int r = row0 + ty * 8 + i;
    if (r < NN) {
      float o[8];
#pragma unroll
      for (int j = 0; j < 8; j++) o[j] = ssp_f(acc[i][j] + bias[tx * 8 + j]);
      float* dst = g_v + (size_t)r * 128 + tx * 8;
      *(float4*)(dst) = make_float4(o[0], o[1], o[2], o[3]);
      *(float4*)(dst + 4) = make_float4(o[4], o[5], o[6], o[7]);
    }
  }
}

// ---------------- readout GEMM: t = ssp(v @ W1 + b1) ; [N,128]x[128,64] ----------------
__global__ __launch_bounds__(256) void k_rogemm(const float* __restrict__ W1,
                                                const float* __restrict__ b1) {
  __shared__ float As[16][64];
  __shared__ float Bs[16][64];
  int tid = threadIdx.x;
  int row0 = blockIdx.x * 64;
  int ty = tid >> 4, tx = tid & 15;
  float acc[4][4];
#pragma unroll
  for (int i = 0; i < 4; i++)
#pragma unroll
    for (int j = 0; j < 4; j++) acc[i][j] = 0.f;

  int a_r = tid >> 2, a_c = (tid & 3) << 2;
  int b_r = tid >> 4, b_c = (tid & 15) << 2;
  int grow = row0 + a_r;
  bool avalid = grow < NN;
  const float* Aptr = g_v + (size_t)(avalid ? grow : 0) * 128 + a_c;

  for (int k0 = 0; k0 < 128; k0 += 16) {
    float4 av = avalid ? *(const float4*)(Aptr + k0) : make_float4(0.f, 0.f, 0.f, 0.f);
    float4 bv = *(const float4*)(W1 + (size_t)(k0 + b_r) * 64 + b_c);
    As[a_c + 0][a_r] = av.x;
    As[a_c + 1][a_r] = av.y;
    As[a_c + 2][a_r] = av.z;
    As[a_c + 3][a_r] = av.w;
    *(float4*)&Bs[b_r][b_c] = bv;
    __syncthreads();
#pragma unroll
    for (int kk = 0; kk < 16; kk++) {
      float a[4], b[4];
      *(float4*)(a) = *(const float4*)&As[kk][ty * 4];
      *(float4*)(b) = *(const float4*)&Bs[kk][tx * 4];
#pragma unroll
      for (int i = 0; i < 4; i++)
#pragma unroll
        for (int j = 0; j < 4; j++) acc[i][j] = fmaf(a[i], b[j], acc[i][j]);
    }
    __syncthreads();
  }
#pragma unroll
  for (int i = 0; i < 4; i++) {
    int r = row0 + ty * 4 + i;
    if (r < NN) {
      float o[4];
#pragma unroll
      for (int j = 0; j < 4; j++) o[j] = ssp_f(acc[i][j] + b1[tx * 4 + j]);
      *(float4*)(g_t + (size_t)r * 64 + tx * 4) = make_float4(o[0], o[1], o[2], o[3]);
    }
  }
}

// ---------------- final: u = t @ W2 + b2, segment-sum over batch ----------------
__global__ void k_zero_out(float* __restrict__ out, int n) {
  int i = blockIdx.x * blockDim.x + threadIdx.x;
  if (i < n) out[i] = 0.f;
}

__global__ void k_u(const int* __restrict__ batch, const float* __restrict__ W2,
                    const float* __restrict__ b2, float* __restrict__ out) {
  int wg = (blockIdx.x * blockDim.x + threadIdx.x) >> 5;
  int lane = threadIdx.x & 31;
  if (wg >= NN) return;
  const float* tr = g_t + (size_t)wg * 64;
  float p = tr[lane] * W2[lane] + tr[lane + 32] * W2[lane + 32];
#pragma unroll
  for (int off = 16; off > 0; off >>= 1) p += __shfl_down_sync(0xffffffffu, p, off);
  if (lane == 0) atomicAdd(&out[batch[wg]], p + b2[0]);
}

// ---------------- launch ----------------
extern "C" void kernel_launch(void* const* d_in, const int* in_sizes, int n_in,
                              void* d_out, int out_size) {
  (void)in_sizes; (void)n_in;
  const int* z = (const int*)d_in[0];
  const float* pos = (const float*)d_in[1];
  const int* batch = (const int*)d_in[2];
  const int* ei = (const int*)d_in[3];
  const float* emb = (const float*)d_in[4];
  const float* dist_W = (const float*)d_in[5];
  const float* dist_b = (const float*)d_in[6];
  const float* Wn = (const float*)d_in[7];
  const float* We = (const float*)d_in[8];
  const float* be = (const float*)d_in[9];
  const float* Wo = (const float*)d_in[10];
  const float* bo = (const float*)d_in[11];
  const float* W1 = (const float*)d_in[12];
  const float* b1 = (const float*)d_in[13];
  const float* W2 = (const float*)d_in[14];
  const float* b2 = (const float*)d_in[15];
  float* out = (float*)d_out;

  const int* row = ei;
  const int* col = ei + EE;

  // CSR build (counting sort by destination row)
  k_zero_cnt<<<(NN + 255) / 256, 256>>>();
  k_hist<<<(EE + 255) / 256, 256>>>(row);
  k_scan<<<1, 1024>>>();
  k_cursor<<<(NN + 255) / 256, 256>>>();
  k_scatter<<<(EE + 255) / 256, 256>>>(row, col, pos);

  // init node features, fold per-layer weights
  k_init_v<<<(NN * HH + 255) / 256, 256>>>(z, emb);
  k_prep<<<dim3(LL, 8), 256>>>(dist_W, dist_b, Wn, We, be, Wo);

  // 6 message-passing layers
  for (int i = 0; i < LL; i++) {
    k_edge<<<(NN * 32 + 255) / 256, 256>>>();
    k_gemm<<<(NN + 127) / 128, 256>>>(i, bo + i * HH);
  }

  // readout
  k_rogemm<<<(NN + 63) / 64, 256>>>(W1, b1);
  k_zero_out<<<(GG + 255) / 256, 256>>>(out, out_size);
  k_u<<<(NN * 32 + 255) / 256, 256>>>(batch, W2, b2, out);
}

// round 5
// speedup vs baseline: 2.0547x; 2.0547x over previous
#include <cuda_runtime.h>
#include <cuda_bf16.h>
#include <math.h>
#include <stdint.h>

#define NN 50000
#define EE 1600000
#define GG 500
#define HH 128
#define NGG 50
#define LL 6

// ---------------- device scratch (static, no allocation) ----------------
__device__ int   g_cnt[NN];
__device__ int   g_rowptr[NN + 1];
__device__ int   g_cursor[NN];
__device__ int   g_bsum[256];
__device__ int   g_scol[EE];
__device__ float g_sdist[EE];
__device__ __align__(16) __nv_bfloat16 g_vb[(size_t)NN * HH];       // node features bf16
__device__ __align__(16) __nv_bfloat16 g_Pb[(size_t)NN * 256];      // [P0|P1] bf16
__device__ __align__(16) __nv_bfloat16 g_Mb[(size_t)LL * HH * 256]; // folded B^T [n][k] bf16
__device__ float g_t[(size_t)NN * 64];

__device__ __forceinline__ float ssp_f(float x) {
  float sp = (x > 15.f) ? x : __logf(1.f + __expf(x));
  return sp - 0.6931471805599453f;
}

// ---------------- CSR build ----------------
__global__ void k_zero_cnt() {
  int i = blockIdx.x * blockDim.x + threadIdx.x;
  if (i < NN) g_cnt[i] = 0;
}

__global__ void k_hist(const int* __restrict__ row) {
  int e = blockIdx.x * blockDim.x + threadIdx.x;
  if (e < EE) atomicAdd(&g_cnt[row[e]], 1);
}

__device__ __forceinline__ int block_incl_scan_256(int x, int* ws) {
  int lane = threadIdx.x & 31, w = threadIdx.x >> 5;
  int incl = x;
#pragma unroll
  for (int off = 1; off < 32; off <<= 1) {
    int y = __shfl_up_sync(0xffffffffu, incl, off);
    if (lane >= off) incl += y;
  }
  if (lane == 31) ws[w] = incl;
  __syncthreads();
  if (threadIdx.x == 0) {
    int s = 0;
#pragma unroll
    for (int j = 0; j < 8; j++) { int t = ws[j]; ws[j] = s; s += t; }
  }
  __syncthreads();
  return incl + ws[w];
}

__global__ void k_scan1() {
  __shared__ int ws[8];
  int i = blockIdx.x * 256 + threadIdx.x;
  int x = (i < NN) ? g_cnt[i] : 0;
  int incl = block_incl_scan_256(x, ws);
  if (i < NN) g_rowptr[i + 1] = incl;
  if (threadIdx.x == 255) g_bsum[blockIdx.x] = incl;
}

__global__ void k_scan2(int nblocks) {
  __shared__ int ws[8];
  int x = (threadIdx.x < nblocks) ? g_bsum[threadIdx.x] : 0;
  int incl = block_incl_scan_256(x, ws);
  if (threadIdx.x < nblocks) g_bsum[threadIdx.x] = incl - x;  // exclusive
}

__global__ void k_scan3() {
  int i = blockIdx.x * 256 + threadIdx.x;
  if (i < NN) {
    int fin = g_rowptr[i + 1] + g_bsum[blockIdx.x];
    g_rowptr[i + 1] = fin;
    g_cursor[i] = fin - g_cnt[i];
    if (i == 0) g_rowptr[0] = 0;
  }
}

__global__ void k_scatter(const int* __restrict__ row, const int* __restrict__ col,
                          const float* __restrict__ pos) {
  int e = blockIdx.x * blockDim.x + threadIdx.x;
  if (e >= EE) return;
  int r = row[e], c = col[e];
  float dx = pos[3 * r + 0] - pos[3 * c + 0];
  float dy = pos[3 * r + 1] - pos[3 * c + 1];
  float dz = pos[3 * r + 2] - pos[3 * c + 2];
  float dist = sqrtf(dx * dx + dy * dy + dz * dz);
  int idx = atomicAdd(&g_cursor[r], 1);
  g_scol[idx] = c;
  g_sdist[idx] = dist;
}

// ---------------- init & weight folding ----------------
__global__ void k_init_v(const int* __restrict__ z, const float* __restrict__ emb) {
  int i = blockIdx.x * blockDim.x + threadIdx.x;
  if (i < NN * HH) {
    int n = i >> 7, f = i & 127;
    g_vb[i] = __float2bfloat16(emb[(z[n] << 7) + f]);
  }
}

// Mb[n][k] (bf16, B^T): M0 = (Wn .* c) @ Wo ; M1 = (Wn .* a) @ Wo
__global__ void k_prep(const float* __restrict__ dist_W, const float* __restrict__ dist_b,
                       const float* __restrict__ Wn, const float* __restrict__ We,
                       const float* __restrict__ be, const float* __restrict__ Wo) {
  int li = blockIdx.x;
  int tid = threadIdx.x;
  __shared__ float sa[128], sc[128];
  if (tid < 128) {
    float a = 0.f, c = 0.f;
    const float* we = We + (size_t)li * NGG * HH + tid;
#pragma unroll 10
    for (int g = 0; g < NGG; g++) {
      float w = we[(size_t)g * HH];
      a = fmaf(dist_W[g], w, a);
      c = fmaf(dist_b[g], w, c);
    }
    sa[tid] = a;
    sc[tid] = c + be[li * HH + tid];
  }
  __syncthreads();
  int k = blockIdx.y * 32 + (tid >> 3);  // K index 0..255
  int o0 = (tid & 7) << 4;               // 16 output cols
  int h = k & 127;
  const float* coef = (k >= 128) ? sa : sc;
  const float* wn = Wn + (size_t)li * HH * HH + (size_t)h * HH;
  const float* wo = Wo + (size_t)li * HH * HH + o0;
  float acc[16];
#pragma unroll
  for (int q = 0; q < 16; q++) acc[q] = 0.f;
  for (int f = 0; f < 128; f++) {
    float wf = wn[f] * coef[f];
    const float* wr = wo + (size_t)f * HH;
#pragma unroll
    for (int q = 0; q < 16; q++) acc[q] = fmaf(wf, wr[q], acc[q]);
  }
  __nv_bfloat16* dst = g_Mb + (size_t)li * HH * 256;
#pragma unroll
  for (int q = 0; q < 16; q++) dst[(size_t)(o0 + q) * 256 + k] = __float2bfloat16(acc[q]);
}

// ---------------- edge aggregation: P0 = sum v[col], P1 = sum dist*v[col] (bf16 io) ----------------
__global__ void k_edge() {
  int wg = (blockIdx.x * blockDim.x + threadIdx.x) >> 5;
  int lane = threadIdx.x & 31;
  if (wg >= NN) return;
  int s = g_rowptr[wg], e = g_rowptr[wg + 1];
  float a0 = 0.f, a1 = 0.f, a2 = 0.f, a3 = 0.f;
  float b0 = 0.f, b1 = 0.f, b2 = 0.f, b3 = 0.f;
  for (int base = s; base < e; base += 32) {
    int j = base + lane;
    int c = 0;
    float d = 0.f;
    if (j < e) { c = g_scol[j]; d = g_sdist[j]; }
    int cnt = min(32, e - base);
#pragma unroll 4
    for (int t = 0; t < cnt; ++t) {
      int cc = __shfl_sync(0xffffffffu, c, t);
      float dd = __shfl_sync(0xffffffffu, d, t);
      uint2 raw = *(const uint2*)(g_vb + ((size_t)cc << 7) + (lane << 2));
      float2 f0 = __bfloat1622float2(*(__nv_bfloat162*)&raw.x);
      float2 f1 = __bfloat1622float2(*(__nv_bfloat162*)&raw.y);
      a0 += f0.x; a1 += f0.y; a2 += f1.x; a3 += f1.y;
      b0 = fmaf(dd, f0.x, b0);
      b1 = fmaf(dd, f0.y, b1);
      b2 = fmaf(dd, f1.x, b2);
      b3 = fmaf(dd, f1.y, b3);
    }
  }
  __nv_bfloat16* p = g_Pb + ((size_t)wg << 8);
  __nv_bfloat162 h0 = __float22bfloat162_rn(make_float2(a0, a1));
  __nv_bfloat162 h1 = __float22bfloat162_rn(make_float2(a2, a3));
  __nv_bfloat162 h2 = __float22bfloat162_rn(make_float2(b0, b1));
  __nv_bfloat162 h3 = __float22bfloat162_rn(make_float2(b2, b3));
  *(uint2*)(p + (lane << 2)) = make_uint2(*(uint32_t*)&h0, *(uint32_t*)&h1);
  *(uint2*)(p + 128 + (lane << 2)) = make_uint2(*(uint32_t*)&h2, *(uint32_t*)&h3);
}

// ---------------- mma.sync bf16 layer GEMM: v = ssp(P @ Mb^T + bo) ----------------
// CTA tile 128(M) x 128(N), K=256, 8 warps (4 along M x 2 along N).
// A/B in padded SMEM: row stride 264 bf16 (528B) -> conflict-free 32-bit frag loads.
#define LDAB 264
#define SMEM_GEMM (2 * 128 * LDAB * 2 + 512)

__device__ __forceinline__ void mma16816(float* d, const uint32_t* a, const uint32_t* b,
                                         const float* c) {
  asm volatile(
      "mma.sync.aligned.m16n8k16.row.col.f32.bf16.bf16.f32 "
      "{%0,%1,%2,%3}, {%4,%5,%6,%7}, {%8,%9}, {%10,%11,%12,%13};\n"
      : "=f"(d[0]), "=f"(d[1]), "=f"(d[2]), "=f"(d[3])
      : "r"(a[0]), "r"(a[1]), "r"(a[2]), "r"(a[3]), "r"(b[0]), "r"(b[1]),
        "f"(c[0]), "f"(c[1]), "f"(c[2]), "f"(c[3]));
}

__global__ __launch_bounds__(256) void k_gemm_mma(int layer, const float* __restrict__ bias) {
  extern __shared__ __nv_bfloat16 sm[];
  __nv_bfloat16* As = sm;                    // [128][LDAB]
  __nv_bfloat16* Bs = sm + 128 * LDAB;       // [128][LDAB]  (B^T: n rows, k cols)
  float* sbias = (float*)(Bs + 128 * LDAB);
  int tid = threadIdx.x;
  int row0 = blockIdx.x * 128;

  // load tiles (A zero-padded at the tail CTA)
  const __nv_bfloat16* Bsrc = g_Mb + (size_t)layer * HH * 256;
#pragma unroll
  for (int it = 0; it < 16; it++) {
    int lin = it * 256 + tid;        // 4096 uint4 per tile
    int r = lin >> 5;                // 32 uint4 per 256-col row
    int c8 = (lin & 31) << 3;
    int gr = row0 + r;
    uint4 va = make_uint4(0, 0, 0, 0);
    if (gr < NN) va = *(const uint4*)(g_Pb + (size_t)gr * 256 + c8);
    *(uint4*)(As + r * LDAB + c8) = va;
    *(uint4*)(Bs + r * LDAB + c8) = *(const uint4*)(Bsrc + (size_t)r * 256 + c8);
  }
  if (tid < 128) sbias[tid] = bias[tid];
  __syncthreads();

  int warp = tid >> 5, lane = tid & 31;
  int mw = warp >> 1, nw = warp & 1;
  int mrow0 = mw * 32, ncol0 = nw * 64;
  int qr = lane >> 2, qc = lane & 3;

  float acc[2][8][4];
#pragma unroll
  for (int mi = 0; mi < 2; mi++)
#pragma unroll
    for (int ni = 0; ni < 8; ni++)
#pragma unroll
      for (int q = 0; q < 4; q++) acc[mi][ni][q] = 0.f;

#pragma unroll
  for (int kk = 0; kk < 16; kk++) {
    int kb = kk * 16 + qc * 2;
    uint32_t a[2][4], b[8][2];
#pragma unroll
    for (int mi = 0; mi < 2; mi++) {
      const __nv_bfloat16* ap = As + (mrow0 + mi * 16 + qr) * LDAB + kb;
      a[mi][0] = *(const uint32_t*)(ap);
      a[mi][1] = *(const uint32_t*)(ap + 8 * LDAB);
      a[mi][2] = *(const uint32_t*)(ap + 8);
      a[mi][3] = *(const uint32_t*)(ap + 8 * LDAB + 8);
    }
#pragma unroll
    for (int ni = 0; ni < 8; ni++) {
      const __nv_bfloat16* bp = Bs + (ncol0 + ni * 8 + qr) * LDAB + kb;
      b[ni][0] = *(const uint32_t*)(bp);
      b[ni][1] = *(const uint32_t*)(bp + 8);
    }
#pragma unroll
    for (int mi = 0; mi < 2; mi++)
#pragma unroll
      for (int ni = 0; ni < 8; ni++) mma16816(acc[mi][ni], a[mi], b[ni], acc[mi][ni]);
  }

  // epilogue: bias + ssp, write bf16
#pragma unroll
  for (int mi = 0; mi < 2; mi++) {
    int r1 = row0 + mrow0 + mi * 16 + qr;
    int r2 = r1 + 8;
#pragma unroll
    for (int ni = 0; ni < 8; ni++) {
      int cc = ncol0 + ni * 8 + qc * 2;
      float bz0 = sbias[cc], bz1 = sbias[cc + 1];
      if (r1 < NN) {
        __nv_bfloat162 o = __float22bfloat162_rn(
            make_float2(ssp_f(acc[mi][ni][0] + bz0), ssp_f(acc[mi][ni][1] + bz1)));
        *(uint32_t*)(g_vb + (size_t)r1 * 128 + cc) = *(uint32_t*)&o;
      }
      if (r2 < NN) {
        __nv_bfloat162 o = __float22bfloat162_rn(
            make_float2(ssp_f(acc[mi][ni][2] + bz0), ssp_f(acc[mi][ni][3] + bz1)));
        *(uint32_t*)(g_vb + (size_t)r2 * 128 + cc) = *(uint32_t*)&o;
      }
    }
  }
}

// ---------------- readout GEMM: t = ssp(v @ W1 + b1) ; [N,128]x[128,64] ----------------
__global__ __launch_bounds__(256) void k_rogemm(const float* __restrict__ W1,
                                                const float* __restrict__ b1) {
  __shared__ float As[16][64];
  __shared__ float Bs[16][64];
  int tid = threadIdx.x;
  int row0 = blockIdx.x * 64;
  int ty = tid >> 4, tx = tid & 15;
  float acc[4][4];
#pragma unroll
  for (int i = 0; i < 4; i++)
#pragma unroll
    for (int j = 0; j < 4; j++) acc[i][j] = 0.f;

  int a_r = tid >> 2, a_c = (tid & 3) << 2;
  int b_r = tid >> 4, b_c = (tid & 15) << 2;
  int grow = row0 + a_r;
  bool avalid = grow < NN;
  const __nv_bfloat16* Aptr = g_vb + (size_t)(avalid ? grow : 0) * 128 + a_c;

  for (int k0 = 0; k0 < 128; k0 += 16) {
    float2 f0 = make_float2(0.f, 0.f), f1 = make_float2(0.f, 0.f);
    if (avalid) {
      uint2 raw = *(const uint2*)(Aptr + k0);
      f0 = __bfloat1622float2(*(__nv_bfloat162*)&raw.x);
      f1 = __bfloat1622float2(*(__nv_bfloat162*)&raw.y);
    }
    float4 bv = *(const float4*)(W1 + (size_t)(k0 + b_r) * 64 + b_c);
    As[a_c + 0][a_r] = f0.x;
    As[a_c + 1][a_r] = f0.y;
    As[a_c + 2][a_r] = f1.x;
    As[a_c + 3][a_r] = f1.y;
    *(float4*)&Bs[b_r][b_c] = bv;
    __syncthreads();
#pragma unroll
    for (int kk = 0; kk < 16; kk++) {
      float a[4], b[4];
      *(float4*)(a) = *(const float4*)&As[kk][ty * 4];
      *(float4*)(b) = *(const float4*)&Bs[kk][tx * 4];
#pragma unroll
      for (int i = 0; i < 4; i++)
#pragma unroll
        for (int j = 0; j < 4; j++) acc[i][j] = fmaf(a[i], b[j], acc[i][j]);
    }
    __syncthreads();
  }
#pragma unroll
  for (int i = 0; i < 4; i++) {
    int r = row0 + ty * 4 + i;
    if (r < NN) {
      float o[4];
#pragma unroll
      for (int j = 0; j < 4; j++) o[j] = ssp_f(acc[i][j] + b1[tx * 4 + j]);
      *(float4*)(g_t + (size_t)r * 64 + tx * 4) = make_float4(o[0], o[1], o[2], o[3]);
    }
  }
}

// ---------------- final: u = t @ W2 + b2, segment-sum over batch ----------------
__global__ void k_zero_out(float* __restrict__ out, int n) {
  int i = blockIdx.x * blockDim.x + threadIdx.x;
  if (i < n) out[i] = 0.f;
}

__global__ void k_u(const int* __restrict__ batch, const float* __restrict__ W2,
                    const float* __restrict__ b2, float* __restrict__ out) {
  int wg = (blockIdx.x * blockDim.x + threadIdx.x) >> 5;
  int lane = threadIdx.x & 31;
  if (wg >= NN) return;
  const float* tr = g_t + (size_t)wg * 64;
  float p = tr[lane] * W2[lane] + tr[lane + 32] * W2[lane + 32];
#pragma unroll
  for (int off = 16; off > 0; off >>= 1) p += __shfl_down_sync(0xffffffffu, p, off);
  if (lane == 0) atomicAdd(&out[batch[wg]], p + b2[0]);
}

// ---------------- launch ----------------
extern "C" void kernel_launch(void* const* d_in, const int* in_sizes, int n_in,
                              void* d_out, int out_size) {
  (void)in_sizes; (void)n_in;
  const int* z = (const int*)d_in[0];
  const float* pos = (const float*)d_in[1];
  const int* batch = (const int*)d_in[2];
  const int* ei = (const int*)d_in[3];
  const float* emb = (const float*)d_in[4];
  const float* dist_W = (const float*)d_in[5];
  const float* dist_b = (const float*)d_in[6];
  const float* Wn = (const float*)d_in[7];
  const float* We = (const float*)d_in[8];
  const float* be = (const float*)d_in[9];
  const float* Wo = (const float*)d_in[10];
  const float* bo = (const float*)d_in[11];
  const float* W1 = (const float*)d_in[12];
  const float* b1 = (const float*)d_in[13];
  const float* W2 = (const float*)d_in[14];
  const float* b2 = (const float*)d_in[15];
  float* out = (float*)d_out;

  const int* row = ei;
  const int* col = ei + EE;

  static bool attr_set = false;
  if (!attr_set) {
    cudaFuncSetAttribute(k_gemm_mma, cudaFuncAttributeMaxDynamicSharedMemorySize, SMEM_GEMM);
    attr_set = true;
  }

  const int nscan = (NN + 255) / 256;  // 196

  // CSR build (counting sort by destination row)
  k_zero_cnt<<<(NN + 255) / 256, 256>>>();
  k_hist<<<(EE + 255) / 256, 256>>>(row);
  k_scan1<<<nscan, 256>>>();
  k_scan2<<<1, 256>>>(nscan);
  k_scan3<<<nscan, 256>>>();
  k_scatter<<<(EE + 255) / 256, 256>>>(row, col, pos);

  // init node features, fold per-layer weights
  k_init_v<<<(NN * HH + 255) / 256, 256>>>(z, emb);
  k_prep<<<dim3(LL, 8), 256>>>(dist_W, dist_b, Wn, We, be, Wo);

  // 6 message-passing layers
  const int ngemm = (NN + 127) / 128;  // 391
  for (int i = 0; i < LL; i++) {
    k_edge<<<(NN * 32 + 255) / 256, 256>>>();
    k_gemm_mma<<<ngemm, 256, SMEM_GEMM>>>(i, bo + i * HH);
  }

  // readout
  k_rogemm<<<(NN + 63) / 64, 256>>>(W1, b1);
  k_zero_out<<<(GG + 255) / 256, 256>>>(out, out_size);
  k_u<<<(NN * 32 + 255) / 256, 256>>>(batch, W2, b2, out);
}

// round 9
// speedup vs baseline: 2.0935x; 1.0189x over previous
#include <cuda_runtime.h>
#include <cuda_bf16.h>
#include <math.h>
#include <stdint.h>

#define NN 50000
#define EE 1600000
#define GG 500
#define HH 128
#define NGG 50
#define LL 6

// ---------------- device scratch (static, no allocation) ----------------
__device__ int   g_cnt[NN];
__device__ int   g_rowptr[NN + 1];
__device__ int   g_cursor[NN];
__device__ int   g_bsum[256];
__device__ __align__(16) uint2 g_ecd[EE];                           // packed (col, dist)
__device__ __align__(16) __nv_bfloat16 g_vb[(size_t)NN * HH];       // node features bf16
__device__ __align__(16) __nv_bfloat16 g_Pb[(size_t)NN * 256];      // [P0|P1] bf16
__device__ __align__(16) __nv_bfloat16 g_Mb[(size_t)LL * HH * 256]; // folded B^T [n][k] bf16

__device__ __forceinline__ float ssp_f(float x) {
  float sp = (x > 15.f) ? x : __logf(1.f + __expf(x));
  return sp - 0.6931471805599453f;
}

// ---------------- CSR build ----------------
__global__ void k_zero_cnt() {
  int i = blockIdx.x * blockDim.x + threadIdx.x;
  if (i < NN) g_cnt[i] = 0;
}

__global__ void k_hist(const int* __restrict__ row) {
  int e = blockIdx.x * blockDim.x + threadIdx.x;
  if (e < EE) atomicAdd(&g_cnt[row[e]], 1);
}

__device__ __forceinline__ int block_incl_scan_256(int x, int* ws) {
  int lane = threadIdx.x & 31, w = threadIdx.x >> 5;
  int incl = x;
#pragma unroll
  for (int off = 1; off < 32; off <<= 1) {
    int y = __shfl_up_sync(0xffffffffu, incl, off);
    if (lane >= off) incl += y;
  }
  if (lane == 31) ws[w] = incl;
  __syncthreads();
  if (threadIdx.x == 0) {
    int s = 0;
#pragma unroll
    for (int j = 0; j < 8; j++) { int t = ws[j]; ws[j] = s; s += t; }
  }
  __syncthreads();
  return incl + ws[w];
}

__global__ void k_scan1() {
  __shared__ int ws[8];
  int i = blockIdx.x * 256 + threadIdx.x;
  int x = (i < NN) ? g_cnt[i] : 0;
  int incl = block_incl_scan_256(x, ws);
  if (i < NN) g_rowptr[i + 1] = incl;
  if (threadIdx.x == 255) g_bsum[blockIdx.x] = incl;
}

__global__ void k_scan2(int nblocks) {
  __shared__ int ws[8];
  int x = (threadIdx.x < nblocks) ? g_bsum[threadIdx.x] : 0;
  int incl = block_incl_scan_256(x, ws);
  if (threadIdx.x < nblocks) g_bsum[threadIdx.x] = incl - x;  // exclusive
}

__global__ void k_scan3() {
  int i = blockIdx.x * 256 + threadIdx.x;
  if (i < NN) {
    int fin = g_rowptr[i + 1] + g_bsum[blockIdx.x];
    g_rowptr[i + 1] = fin;
    g_cursor[i] = fin - g_cnt[i];
    if (i == 0) g_rowptr[0] = 0;
  }
}

__global__ void k_scatter(const int* __restrict__ row, const int* __restrict__ col,
                          const float* __restrict__ pos) {
  int e = blockIdx.x * blockDim.x + threadIdx.x;
  if (e >= EE) return;
  int r = row[e], c = col[e];
  float dx = pos[3 * r + 0] - pos[3 * c + 0];
  float dy = pos[3 * r + 1] - pos[3 * c + 1];
  float dz = pos[3 * r + 2] - pos[3 * c + 2];
  float dist = sqrtf(dx * dx + dy * dy + dz * dz);
  int idx = atomicAdd(&g_cursor[r], 1);
  g_ecd[idx] = make_uint2((uint32_t)c, __float_as_uint(dist));
}

// ---------------- init & weight folding ----------------
__global__ void k_init_v(const int* __restrict__ z, const float* __restrict__ emb) {
  int i = blockIdx.x * blockDim.x + threadIdx.x;
  if (i < NN * HH) {
    int n = i >> 7, f = i & 127;
    g_vb[i] = __float2bfloat16(emb[(z[n] << 7) + f]);
  }
}

// Mb[n][k] (bf16, B^T): M0 = (Wn .* c) @ Wo ; M1 = (Wn .* a) @ Wo
__global__ void k_prep(const float* __restrict__ dist_W, const float* __restrict__ dist_b,
                       const float* __restrict__ Wn, const float* __restrict__ We,
                       const float* __restrict__ be, const float* __restrict__ Wo) {
  int li = blockIdx.x;
  int tid = threadIdx.x;
  __shared__ float sa[128], sc[128];
  if (tid < 128) {
    float a = 0.f, c = 0.f;
    const float* we = We + (size_t)li * NGG * HH + tid;
#pragma unroll 10
    for (int g = 0; g < NGG; g++) {
      float w = we[(size_t)g * HH];
      a = fmaf(dist_W[g], w, a);
      c = fmaf(dist_b[g], w, c);
    }
    sa[tid] = a;
    sc[tid] = c + be[li * HH + tid];
  }
  __syncthreads();
  int k = blockIdx.y * 32 + (tid >> 3);  // K index 0..255
  int o0 = (tid & 7) << 4;               // 16 output cols
  int h = k & 127;
  const float* coef = (k >= 128) ? sa : sc;
  const float* wn = Wn + (size_t)li * HH * HH + (size_t)h * HH;
  const float* wo = Wo + (size_t)li * HH * HH + o0;
  float acc[16];
#pragma unroll
  for (int q = 0; q < 16; q++) acc[q] = 0.f;
  for (int f = 0; f < 128; f++) {
    float wf = wn[f] * coef[f];
    const float* wr = wo + (size_t)f * HH;
#pragma unroll
    for (int q = 0; q < 16; q++) acc[q] = fmaf(wf, wr[q], acc[q]);
  }
  __nv_bfloat16* dst = g_Mb + (size_t)li * HH * 256;
#pragma unroll
  for (int q = 0; q < 16; q++) dst[(size_t)(o0 + q) * 256 + k] = __float2bfloat16(acc[q]);
}

// ---------------- edge aggregation: P0 = sum v[col], P1 = sum dist*v[col] (bf16 io) ----------------
__global__ void k_edge() {
  int wg = (blockIdx.x * blockDim.x + threadIdx.x) >> 5;
  int lane = threadIdx.x & 31;
  if (wg >= NN) return;
  int s = g_rowptr[wg], e = g_rowptr[wg + 1];
  float a0 = 0.f, a1 = 0.f, a2 = 0.f, a3 = 0.f;
  float b0 = 0.f, b1 = 0.f, b2 = 0.f, b3 = 0.f;
  for (int base = s; base < e; base += 32) {
    int j = base + lane;
    int c = 0;
    float d = 0.f;
    if (j < e) {
      uint2 cd = g_ecd[j];
      c = (int)cd.x;
      d = __uint_as_float(cd.y);
    }
    int cnt = min(32, e - base);
#pragma unroll 4
    for (int t = 0; t < cnt; ++t) {
      int cc = __shfl_sync(0xffffffffu, c, t);
      float dd = __shfl_sync(0xffffffffu, d, t);
      uint2 raw = *(const uint2*)(g_vb + ((size_t)cc << 7) + (lane << 2));
      float2 f0 = __bfloat1622float2(*(__nv_bfloat162*)&raw.x);
      float2 f1 = __bfloat1622float2(*(__nv_bfloat162*)&raw.y);
      a0 += f0.x; a1 += f0.y; a2 += f1.x; a3 += f1.y;
      b0 = fmaf(dd, f0.x, b0);
      b1 = fmaf(dd, f0.y, b1);
      b2 = fmaf(dd, f1.x, b2);
      b3 = fmaf(dd, f1.y, b3);
    }
  }
  __nv_bfloat16* p = g_Pb + ((size_t)wg << 8);
  __nv_bfloat162 h0 = __float22bfloat162_rn(make_float2(a0, a1));
  __nv_bfloat162 h1 = __float22bfloat162_rn(make_float2(a2, a3));
  __nv_bfloat162 h2 = __float22bfloat162_rn(make_float2(b0, b1));
  __nv_bfloat162 h3 = __float22bfloat162_rn(make_float2(b2, b3));
  *(uint2*)(p + (lane << 2)) = make_uint2(*(uint32_t*)&h0, *(uint32_t*)&h1);
  *(uint2*)(p + 128 + (lane << 2)) = make_uint2(*(uint32_t*)&h2, *(uint32_t*)&h3);
}

// ---------------- mma.sync bf16 layer GEMM: v = ssp(P @ Mb^T + bo) ----------------
// CTA tile 128(M) x 128(N), K=256, 8 warps (4 along M x 2 along N).
#define LDAB 264
#define SMEM_GEMM (2 * 128 * LDAB * 2 + 512)

__device__ __forceinline__ void mma16816(float* d, const uint32_t* a, const uint32_t* b,
                                         const float* c) {
  asm volatile(
      "mma.sync.aligned.m16n8k16.row.col.f32.bf16.bf16.f32 "
      "{%0,%1,%2,%3}, {%4,%5,%6,%7}, {%8,%9}, {%10,%11,%12,%13};\n"
      : "=f"(d[0]), "=f"(d[1]), "=f"(d[2]), "=f"(d[3])
      : "r"(a[0]), "r"(a[1]), "r"(a[2]), "r"(a[3]), "r"(b[0]), "r"(b[1]),
        "f"(c[0]), "f"(c[1]), "f"(c[2]), "f"(c[3]));
}

__global__ __launch_bounds__(256) void k_gemm_mma(int layer, const float* __restrict__ bias) {
  extern __shared__ __nv_bfloat16 sm[];
  __nv_bfloat16* As = sm;                    // [128][LDAB]
  __nv_bfloat16* Bs = sm + 128 * LDAB;       // [128][LDAB]  (B^T: n rows, k cols)
  float* sbias = (float*)(Bs + 128 * LDAB);
  int tid = threadIdx.x;
  int row0 = blockIdx.x * 128;

  const __nv_bfloat16* Bsrc = g_Mb + (size_t)layer * HH * 256;
#pragma unroll
  for (int it = 0; it < 16; it++) {
    int lin = it * 256 + tid;        // 4096 uint4 per tile
    int r = lin >> 5;
    int c8 = (lin & 31) << 3;
    int gr = row0 + r;
    uint4 va = make_uint4(0, 0, 0, 0);
    if (gr < NN) va = *(const uint4*)(g_Pb + (size_t)gr * 256 + c8);
    *(uint4*)(As + r * LDAB + c8) = va;
    *(uint4*)(Bs + r * LDAB + c8) = *(const uint4*)(Bsrc + (size_t)r * 256 + c8);
  }
  if (tid < 128) sbias[tid] = bias[tid];
  __syncthreads();

  int warp = tid >> 5, lane = tid & 31;
  int mw = warp >> 1, nw = warp & 1;
  int mrow0 = mw * 32, ncol0 = nw * 64;
  int qr = lane >> 2, qc = lane & 3;

  float acc[2][8][4];
#pragma unroll
  for (int mi = 0; mi < 2; mi++)
#pragma unroll
    for (int ni = 0; ni < 8; ni++)
#pragma unroll
      for (int q = 0; q < 4; q++) acc[mi][ni][q] = 0.f;

#pragma unroll
  for (int kk = 0; kk < 16; kk++) {
    int kb = kk * 16 + qc * 2;
    uint32_t a[2][4], b[8][2];
#pragma unroll
    for (int mi = 0; mi < 2; mi++) {
      const __nv_bfloat16* ap = As + (mrow0 + mi * 16 + qr) * LDAB + kb;
      a[mi][0] = *(const uint32_t*)(ap);
      a[mi][1] = *(const uint32_t*)(ap + 8 * LDAB);
      a[mi][2] = *(const uint32_t*)(ap + 8);
      a[mi][3] = *(const uint32_t*)(ap + 8 * LDAB + 8);
    }
#pragma unroll
    for (int ni = 0; ni < 8; ni++) {
      const __nv_bfloat16* bp = Bs + (ncol0 + ni * 8 + qr) * LDAB + kb;
      b[ni][0] = *(const uint32_t*)(bp);
      b[ni][1] = *(const uint32_t*)(bp + 8);
    }
#pragma unroll
    for (int mi = 0; mi < 2; mi++)
#pragma unroll
      for (int ni = 0; ni < 8; ni++) mma16816(acc[mi][ni], a[mi], b[ni], acc[mi][ni]);
  }

  // epilogue: bias + ssp, write bf16
#pragma unroll
  for (int mi = 0; mi < 2; mi++) {
    int r1 = row0 + mrow0 + mi * 16 + qr;
    int r2 = r1 + 8;
#pragma unroll
    for (int ni = 0; ni < 8; ni++) {
      int cc = ncol0 + ni * 8 + qc * 2;
      float bz0 = sbias[cc], bz1 = sbias[cc + 1];
      if (r1 < NN) {
        __nv_bfloat162 o = __float22bfloat162_rn(
            make_float2(ssp_f(acc[mi][ni][0] + bz0), ssp_f(acc[mi][ni][1] + bz1)));
        *(uint32_t*)(g_vb + (size_t)r1 * 128 + cc) = *(uint32_t*)&o;
      }
      if (r2 < NN) {
        __nv_bfloat162 o = __float22bfloat162_rn(
            make_float2(ssp_f(acc[mi][ni][2] + bz0), ssp_f(acc[mi][ni][3] + bz1)));
        *(uint32_t*)(g_vb + (size_t)r2 * 128 + cc) = *(uint32_t*)&o;
      }
    }
  }
}

// ---------------- fused fp32 readout: out += ssp(v@W1+b1)@W2 + b2 (segment-summed) ----------------
// Identical math to the R4 two-kernel chain (fp32 FFMA, fp32 W1/W2), but the
// W2-dot happens in-register with a 16-lane shuffle reduce; no g_t round-trip.
__global__ __launch_bounds__(256) void k_ro(const float* __restrict__ W1,
                                            const float* __restrict__ b1,
                                            const float* __restrict__ W2,
                                            const float* __restrict__ b2,
                                            const int* __restrict__ batch,
                                            float* __restrict__ out) {
  __shared__ float As[16][64];
  __shared__ float Bs[16][64];
  __shared__ float sb1[64], sW2[64];
  int tid = threadIdx.x;
  int row0 = blockIdx.x * 64;
  int ty = tid >> 4, tx = tid & 15;
  float acc[4][4];
#pragma unroll
  for (int i = 0; i < 4; i++)
#pragma unroll
    for (int j = 0; j < 4; j++) acc[i][j] = 0.f;

  int a_r = tid >> 2, a_c = (tid & 3) << 2;
  int b_r = tid >> 4, b_c = (tid & 15) << 2;
  int grow = row0 + a_r;
  bool avalid = grow < NN;
  const __nv_bfloat16* Aptr = g_vb + (size_t)(avalid ? grow : 0) * 128 + a_c;
  if (tid < 64) { sb1[tid] = b1[tid]; sW2[tid] = W2[tid]; }

  for (int k0 = 0; k0 < 128; k0 += 16) {
    float2 f0 = make_float2(0.f, 0.f), f1 = make_float2(0.f, 0.f);
    if (avalid) {
      uint2 raw = *(const uint2*)(Aptr + k0);
      f0 = __bfloat1622float2(*(__nv_bfloat162*)&raw.x);
      f1 = __bfloat1622float2(*(__nv_bfloat162*)&raw.y);
    }
    float4 bv = *(const float4*)(W1 + (size_t)(k0 + b_r) * 64 + b_c);
    As[a_c + 0][a_r] = f0.x;
    As[a_c + 1][a_r] = f0.y;
    As[a_c + 2][a_r] = f1.x;
    As[a_c + 3][a_r] = f1.y;
    *(float4*)&Bs[b_r][b_c] = bv;
    __syncthreads();
#pragma unroll
    for (int kk = 0; kk < 16; kk++) {
      float a[4], b[4];
      *(float4*)(a) = *(const float4*)&As[kk][ty * 4];
      *(float4*)(b) = *(const float4*)&Bs[kk][tx * 4];
#pragma unroll
      for (int i = 0; i < 4; i++)
#pragma unroll
        for (int j = 0; j < 4; j++) acc[i][j] = fmaf(a[i], b[j], acc[i][j]);
    }
    __syncthreads();
  }

  float bz2 = b2[0];
#pragma unroll
  for (int i = 0; i < 4; i++) {
    int r = row0 + ty * 4 + i;
    float p = 0.f;
#pragma unroll
    for (int j = 0; j < 4; j++)
      p = fmaf(ssp_f(acc[i][j] + sb1[tx * 4 + j]), sW2[tx * 4 + j], p);
    // reduce across the 16 tx-lanes holding this row (contiguous half-warp)
    p += __shfl_xor_sync(0xffffffffu, p, 1);
    p += __shfl_xor_sync(0xffffffffu, p, 2);
    p += __shfl_xor_sync(0xffffffffu, p, 4);
    p += __shfl_xor_sync(0xffffffffu, p, 8);
    if (tx == 0 && r < NN) atomicAdd(&out[batch[r]], p + bz2);
  }
}

// ---------------- misc ----------------
__global__ void k_zero_out(float* __restrict__ out, int n) {
  int i = blockIdx.x * blockDim.x + threadIdx.x;
  if (i < n) out[i] = 0.f;
}

// ---------------- launch ----------------
extern "C" void kernel_launch(void* const* d_in, const int* in_sizes, int n_in,
                              void* d_out, int out_size) {
  (void)in_sizes; (void)n_in;
  const int* z = (const int*)d_in[0];
  const float* pos = (const float*)d_in[1];
  const int* batch = (const int*)d_in[2];
  const int* ei = (const int*)d_in[3];
  const float* emb = (const float*)d_in[4];
  const float* dist_W = (const float*)d_in[5];
  const float* dist_b = (const float*)d_in[6];
  const float* Wn = (const float*)d_in[7];
  const float* We = (const float*)d_in[8];
  const float* be = (const float*)d_in[9];
  const float* Wo = (const float*)d_in[10];
  const float* bo = (const float*)d_in[11];
  const float* W1 = (const float*)d_in[12];
  const float* b1 = (const float*)d_in[13];
  const float* W2 = (const float*)d_in[14];
  const float* b2 = (const float*)d_in[15];
  float* out = (float*)d_out;

  const int* row = ei;
  const int* col = ei + EE;

  static bool attr_set = false;
  if (!attr_set) {
    cudaFuncSetAttribute(k_gemm_mma, cudaFuncAttributeMaxDynamicSharedMemorySize, SMEM_GEMM);
    attr_set = true;
  }

  const int nscan = (NN + 255) / 256;  // 196

  // CSR build (counting sort by destination row)
  k_zero_cnt<<<(NN + 255) / 256, 256>>>();
  k_hist<<<(EE + 255) / 256, 256>>>(row);
  k_scan1<<<nscan, 256>>>();
  k_scan2<<<1, 256>>>(nscan);
  k_scan3<<<nscan, 256>>>();
  k_scatter<<<(EE + 255) / 256, 256>>>(row, col, pos);

  // init node features, fold per-layer weights
  k_init_v<<<(NN * HH + 255) / 256, 256>>>(z, emb);
  k_prep<<<dim3(LL, 8), 256>>>(dist_W, dist_b, Wn, We, be, Wo);

  // 6 message-passing layers
  const int ngemm = (NN + 127) / 128;  // 391
  for (int i = 0; i < LL; i++) {
    k_edge<<<(NN * 32 + 255) / 256, 256>>>();
    k_gemm_mma<<<ngemm, 256, SMEM_GEMM>>>(i, bo + i * HH);
  }

  // fused fp32 readout
  k_zero_out<<<(GG + 255) / 256, 256>>>(out, out_size);
  k_ro<<<(NN + 63) / 64, 256>>>(W1, b1, W2, b2, batch, out);
}